// round 12
// baseline (speedup 1.0000x reference)
#include <cuda_runtime.h>
#include <cuda_bf16.h>

// Problem constants:
//   B = 128 rows, L = 262144 input cols
//   CROP_NUM = 26214, OUT_LEN = 235930
//   out[i, j] = audio[i, j]             for j <  starts[i]
//   out[i, j] = audio[i, j + CROP_NUM]  for j >= starts[i]
//
// 2D-grid formulation (blockIdx.y = row): `start` is block-uniform, no
// per-vector div/mod, no row-straddle path. OUT_LEN % 4 == 2, so odd rows
// get a 2-element alignment prefix; 58982 aligned float4 vectors per row
// + 2 scalar leftovers.
//
// Store policy experiment (last untested lever): __stwt write-through.
// Output is write-once/never-read; writing through L2 avoids displacing
// the replay-resident input (120.8 MB vs 126 MB L2). Tested alternatives:
// default ~35-36.5us, __stcs ~36us, evict_last+stcs ~36us (all within
// +/-1.3us noise). If __stwt is also neutral, DRAM R/W is the hard floor.

#define L_IN     262144u
#define CROP_NUM 26214u
#define OUT_LEN  235930u
#define ROW_VECS 58982u          // full aligned float4 vectors per row
#define BLK_VECS 1024u           // 256 threads * ILP 4
#define GRID_X   58u             // ceil(58982 / 1024)

__global__ __launch_bounds__(256)
void Crop_21345987461560_kernel(const float* __restrict__ audio,
                                const int*   __restrict__ starts,
                                float*       __restrict__ out)
{
    const unsigned int row = blockIdx.y;
    const unsigned int pre = (row & 1u) << 1;                 // 0 or 2
    const unsigned int start = (unsigned int)__ldg(&starts[row]);  // uniform
    const float* __restrict__ rowp = audio + (size_t)row * L_IN;

    // row*OUT_LEN + pre is a multiple of 4 -> aligned float4 view.
    float4* __restrict__ out4 =
        reinterpret_cast<float4*>(out + (size_t)row * OUT_LEN + pre);

    const unsigned int v0 = blockIdx.x * BLK_VECS + threadIdx.x;

    #pragma unroll
    for (unsigned int k = 0; k < 4u; ++k) {
        unsigned int v = v0 + k * 256u;
        if (v < ROW_VECS) {
            unsigned int j0 = pre + v * 4u;                   // even
            float4 r;
            if (j0 >= start) {
                // Fully post-crop: contiguous shifted (8B-aligned) -> 2x LDG.64
                const float2* p = reinterpret_cast<const float2*>(rowp + j0 + CROP_NUM);
                float2 a = __ldg(p);
                float2 b = __ldg(p + 1);
                r = make_float4(a.x, a.y, b.x, b.y);
            } else if (j0 + 3u < start) {
                // Fully pre-crop: contiguous (8/16B-aligned) -> 2x LDG.64
                const float2* p = reinterpret_cast<const float2*>(rowp + j0);
                float2 a = __ldg(p);
                float2 b = __ldg(p + 1);
                r = make_float4(a.x, a.y, b.x, b.y);
            } else {
                // Straddles the crop boundary (one vector per row): scalar
                unsigned int j;
                j = j0;      r.x = __ldg(&rowp[j + (j >= start ? CROP_NUM : 0u)]);
                j = j0 + 1u; r.y = __ldg(&rowp[j + (j >= start ? CROP_NUM : 0u)]);
                j = j0 + 2u; r.z = __ldg(&rowp[j + (j >= start ? CROP_NUM : 0u)]);
                j = j0 + 3u; r.w = __ldg(&rowp[j + (j >= start ? CROP_NUM : 0u)]);
            }
            __stwt(out4 + v, r);   // write-through: don't pollute L2
        }
    }

    // 2 leftover scalar elements per row: prefix (j=0,1) on odd rows,
    // suffix (j=OUT_LEN-2, OUT_LEN-1) on even rows.
    if (blockIdx.x == 0 && threadIdx.x < 2u) {
        unsigned int j = (row & 1u) ? threadIdx.x
                                    : (OUT_LEN - 2u + threadIdx.x);
        float val = __ldg(&rowp[j + (j >= start ? CROP_NUM : 0u)]);
        __stwt(out + (size_t)row * OUT_LEN + j, val);
    }
}

extern "C" void kernel_launch(void* const* d_in, const int* in_sizes, int n_in,
                              void* d_out, int out_size)
{
    const float* audio  = (const float*)d_in[0];   // [128, 262144] float32
    const int*   starts = (const int*)d_in[1];     // [128] int32
    float*       out    = (float*)d_out;           // [128, 235930] float32

    dim3 grid(GRID_X, 128u, 1u);                   // 58 x 128 = 7424 blocks
    Crop_21345987461560_kernel<<<grid, 256>>>(audio, starts, out);
}